// round 16
// baseline (speedup 1.0000x reference)
#include <cuda_runtime.h>
#include <math.h>

#define Bsz 64
#define Ssz 512
#define Hsz 400
#define Vsz 32000
#define Lsz 16
#define HC   8
#define HCW  50
#define RBLKS 200          // recurrence: 25 jtiles(16 h) x 8 bgroups(8 b)
#define SBLKS 512          // score: 64 b x 8 hc
#define NBLK 712
#define BH   (Bsz * Hsz)
#define HP   404           // hS pitch (floats), bank-conflict-free

// ---------------- data globals ----------------
__device__ float g_hHist[Lsz + 1][BH];
__device__ float g_x[BH];
__device__ float g_xB[Lsz * BH];
__device__ float g_giB[Lsz][Bsz][1200];
__device__ float g_encT[Bsz][Hsz][Ssz];
__device__ float g_scpart4[4][HC][Bsz][Ssz];   // 4-deep ring (4 MB)

// ---------------- sync state ----------------
// phase-0 barrier armed by reset: 712 = 89 x 8
__device__ int g_subBar[89 * 64];
__device__ int g_barRoot, g_barFlag[8 * 64];
// loop sync, zeroed in phase 0
#define OFF_BATCHCNT  0
#define OFF_BATCHFLAG (OFF_BATCHCNT + 16)
#define OFF_SUBH      (OFF_BATCHFLAG + 16*8*64)
#define OFF_HROOT     (OFF_SUBH + 17*25*64)
#define OFF_HFLAG     (OFF_HROOT + 17)
#define OFF_TSUB      (OFF_HFLAG + 17*8*64)
#define OFF_TROOT     (OFF_TSUB + 32*64)
#define OFF_TFLAG     (OFF_TROOT + 1)
#define OFF_CNTBT     (OFF_TFLAG + 8*64)
#define OFF_TAILCNT   (OFF_CNTBT + 16*64)
#define OFF_FUSEDCNT  (OFF_TAILCNT + 64*64)
#define OFF_FUSEDFLAG (OFF_FUSEDCNT + 16)
#define SYNC_WORDS    (OFF_FUSEDFLAG + 16*8*64)
__device__ int g_sync[SYNC_WORDS];

// ---------------- f32x2 helpers ----------------
__device__ __forceinline__ unsigned long long pk2(float x, float y) {
    unsigned long long r;
    asm("mov.b64 %0, {%1, %2};" : "=l"(r) : "f"(x), "f"(y));
    return r;
}
__device__ __forceinline__ void ffma2(unsigned long long& d,
                                      unsigned long long a, unsigned long long b) {
    asm("fma.rn.f32x2 %0, %1, %2, %0;" : "+l"(d) : "l"(a), "l"(b));
}
__device__ __forceinline__ float2 up2(unsigned long long v) {
    float2 f;
    asm("mov.b64 {%0, %1}, %2;" : "=f"(f.x), "=f"(f.y) : "l"(v));
    return f;
}

// ---------------- sync primitives ----------------
__device__ __forceinline__ void wait_flag_m(int* flagArr, int lane) {
    if (threadIdx.x == 0) {
        int v;
        int* p = &flagArr[lane * 64];
        while (true) {
            asm volatile("ld.acquire.gpu.b32 %0, [%1];" : "=r"(v) : "l"(p) : "memory");
            if (v) break;
            __nanosleep(32);
        }
    }
    __syncthreads();
}
__device__ __forceinline__ void wait_ge(int* word, int target) {
    if (threadIdx.x == 0) {
        int v;
        while (true) {
            asm volatile("ld.acquire.gpu.b32 %0, [%1];" : "=r"(v) : "l"(word) : "memory");
            if (v >= target) break;
            __nanosleep(32);
        }
    }
    __syncthreads();
}
__device__ __forceinline__ void set_flags(int* flagArr) {
    #pragma unroll
    for (int c = 0; c < 8; c++)
        asm volatile("st.release.gpu.b32 [%0], %1;" :: "l"(&flagArr[c * 64]), "r"(1) : "memory");
}
__device__ __forceinline__ void arrive_m(int* subs, int subIdx, int subTarget,
                                         int* root, int rootTarget, int* flagArr) {
    __threadfence();
    __syncthreads();
    if (threadIdx.x == 0) {
        int old = atomicAdd(&subs[subIdx * 64], 1);
        if (old == subTarget - 1) {
            int r = atomicAdd(root, 1);
            if (r == rootTarget - 1) set_flags(flagArr);
        }
    }
}

// ---------------- reset: arm only the phase-0 barrier ----------------
__global__ __launch_bounds__(256) void reset_kernel() {
    int i = threadIdx.x;
    for (int k = i; k < 89 * 64; k += 256) g_subBar[k] = 0;
    for (int k = i; k < 8 * 64; k += 256) g_barFlag[k] = 0;
    if (i == 0) g_barRoot = 0;
}

// ================= persistent kernel =================
__global__ __launch_bounds__(128, 8) void persist_kernel(
    const float* __restrict__ eh,
    const float* __restrict__ enc,
    const int* __restrict__ lens,
    const int* __restrict__ uttrs,
    const int* __restrict__ targets,
    const int* __restrict__ slot_p,
    const int* __restrict__ use_tf_p,
    const float* __restrict__ emb,
    const float* __restrict__ slot_emb,
    const float* __restrict__ Wih,
    const float* __restrict__ Whh,
    const float* __restrict__ bih,
    const float* __restrict__ bhh,
    float* __restrict__ out,
    int out_size, int write_preds)
{
    __shared__ float pool[6500];   // 26 KB (8 blocks/SM)
    int bx = blockIdx.x;
    int tid = threadIdx.x;
    int gidx = bx * 128 + tid;
    const int nt = NBLK * 128;
    int lane8 = bx & 7;

    // ============ Phase 0: zero sync + preds pad, init h0/x, xbuild ============
    {
        for (int i = gidx; i < SYNC_WORDS; i += nt) g_sync[i] = 0;
        for (int i = (Bsz * Lsz * Vsz) + gidx; i < out_size; i += nt)
            out[i] = 0.f;
        int slot = slot_p[0];
        for (int i = gidx; i < BH; i += nt) {
            g_hHist[0][i] = eh[i];
            g_x[i] = slot_emb[slot * Hsz + i % Hsz];
        }
        for (int i = gidx; i < Lsz * Bsz * 100; i += nt) {
            int row = i / 100, q = i % 100;
            int t = row >> 6, b = row & 63;
            const float* src = (t == 0) ? (slot_emb + slot * Hsz)
                                        : (emb + (size_t)targets[b * Lsz + (t - 1)] * Hsz);
            ((float4*)(g_xB + (size_t)row * Hsz))[q] = ((const float4*)src)[q];
        }
    }
    arrive_m(g_subBar, bx % 89, 8, &g_barRoot, 89, g_barFlag);   // 712 = 89 x 8
    wait_flag_m(g_barFlag, lane8);

    int tf = use_tf_p[0];

    if (bx < RBLKS) {
        // ============ recurrence: gemm+gates fused, full K, 1 rendezvous/step ============
        float* hS = pool;                 // [8][HP]
        float* xS = pool + 8 * HP;        // [8][HP] (only when inline gi)
        int jt = bx / 8;                  // 0..24
        int bg = bx % 8;                  // 0..7
        int jj = tid >> 3;                // 0..15
        int tb = tid & 7;                 // 0..7
        int j = jt * 16 + jj;             // 0..399
        int b = bg * 8 + tb;

        float bi_r = bih[j], bi_z = bih[400 + j], bi_n = bih[800 + j];
        float bh_r = bhh[j], bh_z = bhh[400 + j], bh_n = bhh[800 + j];
        const float* wr = Whh + (size_t)j * Hsz;
        const float* wz = Whh + (size_t)(400 + j) * Hsz;
        const float* wn = Whh + (size_t)(800 + j) * Hsz;
        const float* vr = Wih + (size_t)j * Hsz;
        const float* vz = Wih + (size_t)(400 + j) * Hsz;
        const float* vn = Wih + (size_t)(800 + j) * Hsz;

        for (int t = 0; t < Lsz; t++) {
            if (t > 0) {
                wait_flag_m(&g_sync[OFF_HFLAG + t * 8 * 64], lane8);
                if (tf) wait_flag_m(&g_sync[OFF_BATCHFLAG + t * 8 * 64], lane8);
                else    wait_flag_m(&g_sync[OFF_FUSEDFLAG + (t - 1) * 8 * 64], lane8);
            }
            bool inline_gi = (t == 0) || !tf;
            const float* hin = g_hHist[t];

            // stage h rows (and x rows if inline)
            __syncthreads();
            for (int i = tid; i < 800; i += 128) {
                int row = i / 100, q = i % 100;
                float4 v = *(const float4*)&hin[(bg * 8 + row) * Hsz + 4 * q];
                *(float4*)&hS[row * HP + 4 * q] = v;
            }
            if (inline_gi) {
                for (int i = tid; i < 800; i += 128) {
                    int row = i / 100, q = i % 100;
                    float4 v = *(const float4*)&g_x[(bg * 8 + row) * Hsz + 4 * q];
                    *(float4*)&xS[row * HP + 4 * q] = v;
                }
            }
            __syncthreads();

            // gh = Whh rows {j,400+j,800+j} . h_b
            const float* hb = &hS[tb * HP];
            unsigned long long aR0 = 0, aR1 = 0, aZ0 = 0, aZ1 = 0, aN0 = 0, aN1 = 0;
            #pragma unroll 4
            for (int k = 0; k < Hsz; k += 4) {
                float4 h4 = *(const float4*)&hb[k];
                float4 r4 = __ldg((const float4*)(wr + k));
                float4 z4 = __ldg((const float4*)(wz + k));
                float4 n4 = __ldg((const float4*)(wn + k));
                unsigned long long h01 = pk2(h4.x, h4.y);
                unsigned long long h23 = pk2(h4.z, h4.w);
                ffma2(aR0, h01, pk2(r4.x, r4.y)); ffma2(aR1, h23, pk2(r4.z, r4.w));
                ffma2(aZ0, h01, pk2(z4.x, z4.y)); ffma2(aZ1, h23, pk2(z4.z, z4.w));
                ffma2(aN0, h01, pk2(n4.x, n4.y)); ffma2(aN1, h23, pk2(n4.z, n4.w));
            }
            float2 fr0 = up2(aR0), fr1 = up2(aR1);
            float2 fz0 = up2(aZ0), fz1 = up2(aZ1);
            float2 fn0 = up2(aN0), fn1 = up2(aN1);
            float gh_r = (fr0.x + fr0.y) + (fr1.x + fr1.y);
            float gh_z = (fz0.x + fz0.y) + (fz1.x + fz1.y);
            float gh_n = (fn0.x + fn0.y) + (fn1.x + fn1.y);

            float gi_r, gi_z, gi_n;
            if (inline_gi) {
                const float* xb = &xS[tb * HP];
                unsigned long long iR0 = 0, iR1 = 0, iZ0 = 0, iZ1 = 0, iN0 = 0, iN1 = 0;
                #pragma unroll 4
                for (int k = 0; k < Hsz; k += 4) {
                    float4 x4 = *(const float4*)&xb[k];
                    float4 r4 = __ldg((const float4*)(vr + k));
                    float4 z4 = __ldg((const float4*)(vz + k));
                    float4 n4 = __ldg((const float4*)(vn + k));
                    unsigned long long x01 = pk2(x4.x, x4.y);
                    unsigned long long x23 = pk2(x4.z, x4.w);
                    ffma2(iR0, x01, pk2(r4.x, r4.y)); ffma2(iR1, x23, pk2(r4.z, r4.w));
                    ffma2(iZ0, x01, pk2(z4.x, z4.y)); ffma2(iZ1, x23, pk2(z4.z, z4.w));
                    ffma2(iN0, x01, pk2(n4.x, n4.y)); ffma2(iN1, x23, pk2(n4.z, n4.w));
                }
                float2 a0 = up2(iR0), a1 = up2(iR1);
                float2 c0 = up2(iZ0), c1 = up2(iZ1);
                float2 d0 = up2(iN0), d1 = up2(iN1);
                gi_r = (a0.x + a0.y) + (a1.x + a1.y);
                gi_z = (c0.x + c0.y) + (c1.x + c1.y);
                gi_n = (d0.x + d0.y) + (d1.x + d1.y);
            } else {
                gi_r = g_giB[t][b][j];
                gi_z = g_giB[t][b][400 + j];
                gi_n = g_giB[t][b][800 + j];
            }

            float r = 1.f / (1.f + expf(-(gi_r + bi_r + gh_r + bh_r)));
            float z = 1.f / (1.f + expf(-(gi_z + bi_z + gh_z + bh_z)));
            float n = tanhf(gi_n + bi_n + r * (gh_n + bh_n));
            float hp = hb[j];
            g_hHist[t + 1][b * Hsz + j] = (1.f - z) * n + z * hp;

            arrive_m(&g_sync[OFF_SUBH + (t + 1) * 25 * 64], jt, 8,
                     &g_sync[OFF_HROOT + t + 1], 25,
                     &g_sync[OFF_HFLAG + (t + 1) * 8 * 64]);
        }
    } else {
        // ============ score pipeline ============
        int fb = bx - RBLKS;

        // ---- duty 1: batch gi unit (t-ordered; 30 units per t) ----
        if (tf && fb < 480) {
            float (*As)[68] = (float(*)[68])pool;
            float (*Ws)[44] = (float(*)[44])(pool + 3400);
            int bt = fb / 30;
            int jbase = (fb % 30) * 40;
            const float* A = g_xB + (size_t)bt * BH;
            int tj = tid / 8, tb2 = tid % 8;
            int b0 = 8 * tb2, j0 = 4 * tj;
            bool active = (tj < 10);

            unsigned long long acc[4][4];
            #pragma unroll
            for (int a = 0; a < 4; a++)
                #pragma unroll
                for (int p = 0; p < 4; p++) acc[a][p] = 0ULL;

            for (int kt = 0; kt < 8; kt++) {
                int kbase = kt * 50;
                __syncthreads();
                for (int i = tid; i < 1600; i += 128) {
                    int q = i >> 6, b2 = i & 63;
                    float2 v = *(const float2*)&A[b2 * Hsz + kbase + 2 * q];
                    As[2 * q + 0][b2] = v.x;
                    As[2 * q + 1][b2] = v.y;
                }
                for (int i = tid; i < 1000; i += 128) {
                    int q = i / 40, jx = i % 40;
                    float2 v = *(const float2*)&Wih[(size_t)(jbase + jx) * Hsz + kbase + 2 * q];
                    Ws[2 * q + 0][jx] = v.x;
                    Ws[2 * q + 1][jx] = v.y;
                }
                __syncthreads();
                if (active) {
                    #pragma unroll 5
                    for (int k = 0; k < 50; k++) {
                        float4 av0 = *(const float4*)&As[k][b0];
                        float4 av1 = *(const float4*)&As[k][b0 + 4];
                        float4 wv  = *(const float4*)&Ws[k][j0];
                        unsigned long long a01 = pk2(av0.x, av0.y);
                        unsigned long long a23 = pk2(av0.z, av0.w);
                        unsigned long long a45 = pk2(av1.x, av1.y);
                        unsigned long long a67 = pk2(av1.z, av1.w);
                        unsigned long long w0 = pk2(wv.x, wv.x);
                        unsigned long long w1 = pk2(wv.y, wv.y);
                        unsigned long long w2 = pk2(wv.z, wv.z);
                        unsigned long long w3 = pk2(wv.w, wv.w);
                        ffma2(acc[0][0], a01, w0); ffma2(acc[0][1], a23, w0);
                        ffma2(acc[0][2], a45, w0); ffma2(acc[0][3], a67, w0);
                        ffma2(acc[1][0], a01, w1); ffma2(acc[1][1], a23, w1);
                        ffma2(acc[1][2], a45, w1); ffma2(acc[1][3], a67, w1);
                        ffma2(acc[2][0], a01, w2); ffma2(acc[2][1], a23, w2);
                        ffma2(acc[2][2], a45, w2); ffma2(acc[2][3], a67, w2);
                        ffma2(acc[3][0], a01, w3); ffma2(acc[3][1], a23, w3);
                        ffma2(acc[3][2], a45, w3); ffma2(acc[3][3], a67, w3);
                    }
                }
            }
            if (active) {
                #pragma unroll
                for (int p = 0; p < 4; p++) {
                    float2 f0 = up2(acc[0][p]);
                    float2 f1 = up2(acc[1][p]);
                    float2 f2 = up2(acc[2][p]);
                    float2 f3 = up2(acc[3][p]);
                    *(float4*)&g_giB[bt][b0 + 2 * p][jbase + j0]     = make_float4(f0.x, f1.x, f2.x, f3.x);
                    *(float4*)&g_giB[bt][b0 + 2 * p + 1][jbase + j0] = make_float4(f0.y, f1.y, f2.y, f3.y);
                }
            }
            __threadfence();
            __syncthreads();
            if (tid == 0) {
                int old = atomicAdd(&g_sync[OFF_BATCHCNT + bt], 1);
                if (old == 29) set_flags(&g_sync[OFF_BATCHFLAG + bt * 8 * 64]);
            }
            __syncthreads();
        }

        // ---- duty 2: transpose stripe ----
        {
            float (*tile)[33] = (float(*)[33])pool;
            int tx = tid & 31, ty = tid >> 5;    // 32 x 4
            for (int tt = fb; tt < Bsz * 16 * 13; tt += SBLKS) {
                int b2 = tt / (16 * 13);
                int rem = tt % (16 * 13);
                int s0 = (rem / 13) * 32;
                int h0 = (rem % 13) * 32;
                __syncthreads();
                #pragma unroll
                for (int i = 0; i < 32; i += 4) {
                    int s = s0 + ty + i, h = h0 + tx;
                    if (h < Hsz) tile[ty + i][tx] = enc[((size_t)b2 * Ssz + s) * Hsz + h];
                }
                __syncthreads();
                #pragma unroll
                for (int i = 0; i < 32; i += 4) {
                    int h = h0 + ty + i, s = s0 + tx;
                    if (h < Hsz) g_encT[b2][h][s] = tile[tx][ty + i];
                }
            }
        }
        arrive_m(&g_sync[OFF_TSUB], fb >> 4, 16, &g_sync[OFF_TROOT], 32,
                 &g_sync[OFF_TFLAG]);
        wait_flag_m(&g_sync[OFF_TFLAG], lane8);

        // ---- duty 3: score loop ----
        float* sh   = pool;
        float* redv = pool + 64;
        int*   redi = (int*)(pool + 192);
        float* flg  = pool + 320;

        int b  = fb >> 3;
        int hc = fb & 7;
        int len = lens[b];

        for (int t = 0; t < Lsz; t++) {
            int slot = t & 3;
            wait_flag_m(&g_sync[OFF_HFLAG + (t + 1) * 8 * 64], lane8);
            if (t >= 4) wait_ge(&g_sync[OFF_TAILCNT + b * 64], t - 3);   // scpart slot reuse

            const float* hnew = g_hHist[t + 1];
            if (tid < HCW)
                sh[tid] = hnew[b * Hsz + hc * HCW + tid];
            __syncthreads();

            int s0 = 4 * tid;
            if (s0 < len) {
                const float4* ep = (const float4*)&g_encT[b][hc * HCW][0] + tid;
                float4 acc = make_float4(0.f, 0.f, 0.f, 0.f);
                #pragma unroll 10
                for (int h = 0; h < HCW; h++) {
                    float hv = sh[h];
                    float4 e = ep[(size_t)h * 128];
                    acc.x += e.x * hv; acc.y += e.y * hv;
                    acc.z += e.z * hv; acc.w += e.w * hv;
                }
                *(float4*)&g_scpart4[slot][hc][b][s0] = acc;
            }

            // zero this block's 1/8 of out row (b, t) before arrival
            {
                float* row = out + (size_t)b * Lsz * Vsz + (size_t)t * Vsz;
                float4* r4 = (float4*)row + hc * 1000;
                for (int i = tid; i < 1000; i += 128) {
                    asm volatile("st.global.cs.v4.f32 [%0], {%1, %2, %3, %4};"
                                 :: "l"(r4 + i), "f"(0.f), "f"(0.f), "f"(0.f), "f"(0.f) : "memory");
                }
            }

            __threadfence();
            __syncthreads();
            if (tid == 0) {
                int old = atomicAdd(&g_sync[OFF_CNTBT + t * Bsz + b], 1);
                flg[0] = (old == HC - 1) ? 1.f : 0.f;
            }
            __syncthreads();
            bool last = (flg[0] != 0.f);

            if (last) {
                __threadfence();
                float v[4];
                #pragma unroll
                for (int q = 0; q < 4; q++) {
                    int s = tid + 128 * q;
                    if (s < len) {
                        float sum = 0.f;
                        #pragma unroll
                        for (int p = 0; p < HC; p++) sum += g_scpart4[slot][p][b][s];
                        v[q] = sum;
                    } else {
                        v[q] = -INFINITY;
                    }
                }
                float mv = v[0]; int mi = tid;
                #pragma unroll
                for (int q = 1; q < 4; q++)
                    if (v[q] > mv) { mv = v[q]; mi = tid + 128 * q; }
                redv[tid] = mv;
                redi[tid] = mi;
                __syncthreads();
                for (int st = 64; st > 0; st >>= 1) {
                    if (tid < st) {
                        float w2 = redv[tid + st];
                        int   i2 = redi[tid + st];
                        if (w2 > redv[tid] || (w2 == redv[tid] && i2 < redi[tid])) {
                            redv[tid] = w2;
                            redi[tid] = i2;
                        }
                    }
                    __syncthreads();
                }
                float m = redv[0];
                int amax = redi[0];
                __syncthreads();

                float e[4], lsum = 0.f;
                #pragma unroll
                for (int q = 0; q < 4; q++) {
                    e[q] = expf(v[q] - m);
                    lsum += e[q];
                }
                redv[tid] = lsum;
                __syncthreads();
                for (int st = 64; st > 0; st >>= 1) {
                    if (tid < st) redv[tid] += redv[tid + st];
                    __syncthreads();
                }
                float inv = 1.f / redv[0];

                float* orow = out + (size_t)b * Lsz * Vsz + (size_t)t * Vsz;
                #pragma unroll
                for (int q = 0; q < 4; q++) {
                    int s = tid + 128 * q;
                    if (s < len)
                        atomicAdd(&orow[uttrs[b * Ssz + s]], e[q] * inv);
                }

                if (tid == 0) {
                    int pred = uttrs[b * Ssz + amax];
                    if (write_preds)
                        out[(size_t)Bsz * Lsz * Vsz + (size_t)t * Bsz + b] = (float)pred;
                    ((int*)flg)[1] = tf ? targets[b * Lsz + t] : pred;
                }
                __syncthreads();
                if (!tf) {
                    int nxt = ((int*)flg)[1];
                    if (tid < 100)
                        ((float4*)(g_x + b * Hsz))[tid] =
                            ((const float4*)(emb + (size_t)nxt * Hsz))[tid];
                }
                // release scpart slot + (if !tf) count toward fusedFlag
                __threadfence();
                __syncthreads();
                if (tid == 0) {
                    atomicAdd(&g_sync[OFF_TAILCNT + b * 64], 1);
                    if (!tf) {
                        int old = atomicAdd(&g_sync[OFF_FUSEDCNT + t], 1);
                        if (old == Bsz - 1)
                            set_flags(&g_sync[OFF_FUSEDFLAG + t * 8 * 64]);
                    }
                }
            }
        }
    }
}

// ---------------- launch ----------------
extern "C" void kernel_launch(void* const* d_in, const int* in_sizes, int n_in,
                              void* d_out, int out_size) {
    const float* eh       = (const float*)d_in[0];
    const float* enc      = (const float*)d_in[1];
    const int*   lens     = (const int*)d_in[2];
    const int*   uttrs    = (const int*)d_in[3];
    const int*   targets  = (const int*)d_in[4];
    const int*   slot     = (const int*)d_in[5];
    const int*   use_tf   = (const int*)d_in[6];
    const float* emb      = (const float*)d_in[7];
    const float* slot_emb = (const float*)d_in[8];
    const float* Wih      = (const float*)d_in[9];
    const float* Whh      = (const float*)d_in[10];
    const float* bih      = (const float*)d_in[11];
    const float* bhh      = (const float*)d_in[12];
    float* out = (float*)d_out;

    int write_preds = out_size > Bsz * Lsz * Vsz;
    reset_kernel<<<1, 256>>>();
    persist_kernel<<<NBLK, 128>>>(eh, enc, lens, uttrs, targets, slot, use_tf,
                                  emb, slot_emb, Wih, Whh, bih, bhh,
                                  out, out_size, write_preds);
}

// round 17
// speedup vs baseline: 1.0926x; 1.0926x over previous
#include <cuda_runtime.h>
#include <math.h>

#define Bsz 64
#define Ssz 512
#define Hsz 400
#define Vsz 32000
#define Lsz 16
#define NPART 8
#define KC   50
#define JT   24
#define HC   8
#define HCW  50
#define GEMM_BLOCKS 400
#define GATE_BLOCKS 64
#define SCORE_BLOCKS 512
#define NBLK 976
#define BH   (Bsz * Hsz)

// ---------------- data globals ----------------
__device__ float g_Gpart[NPART][Bsz][2400];
__device__ float g_hHist[Lsz + 1][BH];
__device__ float g_x[BH];
__device__ float g_xB[Lsz * BH];
__device__ float g_giB[Lsz][Bsz][1200];
__device__ float g_encT[Bsz][Hsz][Ssz];
__device__ float g_scpart[2][HC][Bsz][Ssz];

// ---------------- sync state ----------------
// phase-0 barrier armed by reset: 976 = 61 x 16
__device__ int g_subBar[61 * 64];
__device__ int g_barRoot, g_barFlag[8 * 64];
// loop sync, zeroed in phase 0
#define OFF_SUBGEMM   0
#define OFF_GEMMROOT  (OFF_SUBGEMM + 16*25*64)
#define OFF_GEMMFLAG  (OFF_GEMMROOT + 16)
#define OFF_SUBH      (OFF_GEMMFLAG + 16*8*64)
#define OFF_HROOT     (OFF_SUBH + 17*8*64)
#define OFF_HFLAG     (OFF_HROOT + 17)
#define OFF_BATCHCNT  (OFF_HFLAG + 17*8*64)
#define OFF_BATCHFLAG (OFF_BATCHCNT + 16)
#define OFF_TSUB      (OFF_BATCHFLAG + 16*8*64)
#define OFF_TROOT     (OFF_TSUB + 32*64)
#define OFF_TFLAG     (OFF_TROOT + 1)
#define OFF_CNTBT     (OFF_TFLAG + 8*64)
#define OFF_TAILCNT   (OFF_CNTBT + 16*64)
#define OFF_FUSEDCNT  (OFF_TAILCNT + 64*64)
#define OFF_FUSEDFLAG (OFF_FUSEDCNT + 16)
#define SYNC_WORDS    (OFF_FUSEDFLAG + 16*8*64)
__device__ int g_sync[SYNC_WORDS];

// ---------------- f32x2 helpers ----------------
__device__ __forceinline__ unsigned long long pk2(float x, float y) {
    unsigned long long r;
    asm("mov.b64 %0, {%1, %2};" : "=l"(r) : "f"(x), "f"(y));
    return r;
}
__device__ __forceinline__ void ffma2(unsigned long long& d,
                                      unsigned long long a, unsigned long long b) {
    asm("fma.rn.f32x2 %0, %1, %2, %0;" : "+l"(d) : "l"(a), "l"(b));
}
__device__ __forceinline__ float2 up2(unsigned long long v) {
    float2 f;
    asm("mov.b64 {%0, %1}, %2;" : "=f"(f.x), "=f"(f.y) : "l"(v));
    return f;
}

// ---------------- sync primitives ----------------
__device__ __forceinline__ void wait_flag_m(int* flagArr, int lane) {
    if (threadIdx.x == 0) {
        int v;
        int* p = &flagArr[lane * 64];
        while (true) {
            asm volatile("ld.acquire.gpu.b32 %0, [%1];" : "=r"(v) : "l"(p) : "memory");
            if (v) break;
            __nanosleep(32);
        }
    }
    __syncthreads();
}
__device__ __forceinline__ void wait_ge(int* word, int target) {
    if (threadIdx.x == 0) {
        int v;
        while (true) {
            asm volatile("ld.acquire.gpu.b32 %0, [%1];" : "=r"(v) : "l"(word) : "memory");
            if (v >= target) break;
            __nanosleep(32);
        }
    }
    __syncthreads();
}
__device__ __forceinline__ void set_flags(int* flagArr) {
    #pragma unroll
    for (int c = 0; c < 8; c++)
        asm volatile("st.release.gpu.b32 [%0], %1;" :: "l"(&flagArr[c * 64]), "r"(1) : "memory");
}
__device__ __forceinline__ void arrive_m(int* subs, int subIdx, int subTarget,
                                         int* root, int rootTarget, int* flagArr) {
    __threadfence();
    __syncthreads();
    if (threadIdx.x == 0) {
        int old = atomicAdd(&subs[subIdx * 64], 1);
        if (old == subTarget - 1) {
            int r = atomicAdd(root, 1);
            if (r == rootTarget - 1) set_flags(flagArr);
        }
    }
}

// ---------------- reset: arm only the phase-0 barrier ----------------
__global__ __launch_bounds__(256) void reset_kernel() {
    int i = threadIdx.x;
    for (int k = i; k < 61 * 64; k += 256) g_subBar[k] = 0;
    for (int k = i; k < 8 * 64; k += 256) g_barFlag[k] = 0;
    if (i == 0) g_barRoot = 0;
}

// ================= persistent kernel =================
__global__ __launch_bounds__(128, 8) void persist_kernel(
    const float* __restrict__ eh,
    const float* __restrict__ enc,
    const int* __restrict__ lens,
    const int* __restrict__ uttrs,
    const int* __restrict__ targets,
    const int* __restrict__ slot_p,
    const int* __restrict__ use_tf_p,
    const float* __restrict__ emb,
    const float* __restrict__ slot_emb,
    const float* __restrict__ Wih,
    const float* __restrict__ Whh,
    const float* __restrict__ bih,
    const float* __restrict__ bhh,
    float* __restrict__ out,
    int out_size, int write_preds)
{
    __shared__ float pool[6700];
    int bx = blockIdx.x;
    int tid = threadIdx.x;
    int gidx = bx * 128 + tid;
    const int nt = NBLK * 128;
    int lane8 = bx & 7;

    // ============ Phase 0: zero sync + FULL output, init h0/x, xbuild ============
    {
        for (int i = gidx; i < SYNC_WORDS; i += nt) g_sync[i] = 0;
        int n4 = out_size / 4;
        for (int i = gidx; i < n4; i += nt) {
            float4* p = (float4*)out + i;
            asm volatile("st.global.cs.v4.f32 [%0], {%1, %2, %3, %4};"
                         :: "l"(p), "f"(0.f), "f"(0.f), "f"(0.f), "f"(0.f) : "memory");
        }
        for (int i = n4 * 4 + gidx; i < out_size; i += nt)
            asm volatile("st.global.cs.f32 [%0], %1;" :: "l"(out + i), "f"(0.f) : "memory");

        int slot = slot_p[0];
        for (int i = gidx; i < BH; i += nt) {
            g_hHist[0][i] = eh[i];
            g_x[i] = slot_emb[slot * Hsz + i % Hsz];
        }
        for (int i = gidx; i < Lsz * Bsz * 100; i += nt) {
            int row = i / 100, q = i % 100;
            int t = row >> 6, b = row & 63;
            const float* src = (t == 0) ? (slot_emb + slot * Hsz)
                                        : (emb + (size_t)targets[b * Lsz + (t - 1)] * Hsz);
            ((float4*)(g_xB + (size_t)row * Hsz))[q] = ((const float4*)src)[q];
        }
    }
    arrive_m(g_subBar, bx % 61, 16, &g_barRoot, 61, g_barFlag);   // 976 = 61 x 16
    wait_flag_m(g_barFlag, lane8);

    int tf = use_tf_p[0];

    if (bx < GEMM_BLOCKS) {
        // ============ gemm role (R7-proven internals) ============
        float (*As)[68]  = (float(*)[68])pool;
        float (*WhS)[28] = (float(*)[28])(pool + 3400);
        float (*WiS)[28] = (float(*)[28])(pool + 4800);
        int jt = bx >> 3, ks = bx & 7;
        int jbase = jt * JT;
        int kbase = ks * KC;
        int tj = tid / 16, tb = tid % 16;
        int b0 = 4 * tb, j0 = 4 * tj;
        bool active = (tj < 6);

        for (int i = tid; i < 600; i += 128) {
            int q = i / JT, j = i % JT;
            float2 v = *(const float2*)&Whh[(size_t)(jbase + j) * Hsz + kbase + 2 * q];
            WhS[2 * q + 0][j] = v.x;
            WhS[2 * q + 1][j] = v.y;
        }
        if (!tf) {
            for (int i = tid; i < 600; i += 128) {
                int q = i / JT, j = i % JT;
                float2 v = *(const float2*)&Wih[(size_t)(jbase + j) * Hsz + kbase + 2 * q];
                WiS[2 * q + 0][j] = v.x;
                WiS[2 * q + 1][j] = v.y;
            }
        }
        __syncthreads();

        for (int t = 0; t < Lsz; t++) {
            if (t > 0) wait_flag_m(&g_sync[OFF_HFLAG + t * 8 * 64], lane8);
            if (!tf && t > 0) wait_flag_m(&g_sync[OFF_FUSEDFLAG + (t - 1) * 8 * 64], lane8);
            const float* hin = g_hHist[t];
            for (int mat = tf ? 1 : 0; mat < 2; mat++) {
                const float* A = mat ? hin : g_x;
                float (*Ws)[28] = mat ? WhS : WiS;
                __syncthreads();
                for (int i = tid; i < 1600; i += 128) {
                    int q = i >> 6, b = i & 63;
                    float2 v = *(const float2*)&A[b * Hsz + kbase + 2 * q];
                    As[2 * q + 0][b] = v.x;
                    As[2 * q + 1][b] = v.y;
                }
                __syncthreads();
                if (active) {
                    unsigned long long acc[4][2];
                    #pragma unroll
                    for (int jj = 0; jj < 4; jj++) { acc[jj][0] = 0ULL; acc[jj][1] = 0ULL; }
                    #pragma unroll 5
                    for (int k = 0; k < KC; k++) {
                        float4 av = *(const float4*)&As[k][b0];
                        float4 wv = *(const float4*)&Ws[k][j0];
                        unsigned long long a01 = pk2(av.x, av.y);
                        unsigned long long a23 = pk2(av.z, av.w);
                        unsigned long long w0 = pk2(wv.x, wv.x);
                        unsigned long long w1 = pk2(wv.y, wv.y);
                        unsigned long long w2 = pk2(wv.z, wv.z);
                        unsigned long long w3 = pk2(wv.w, wv.w);
                        ffma2(acc[0][0], a01, w0); ffma2(acc[0][1], a23, w0);
                        ffma2(acc[1][0], a01, w1); ffma2(acc[1][1], a23, w1);
                        ffma2(acc[2][0], a01, w2); ffma2(acc[2][1], a23, w2);
                        ffma2(acc[3][0], a01, w3); ffma2(acc[3][1], a23, w3);
                    }
                    int obase = mat * 1200 + jbase + j0;
                    #pragma unroll
                    for (int bb = 0; bb < 4; bb++) {
                        float v0 = (bb & 1) ? up2(acc[0][bb >> 1]).y : up2(acc[0][bb >> 1]).x;
                        float v1 = (bb & 1) ? up2(acc[1][bb >> 1]).y : up2(acc[1][bb >> 1]).x;
                        float v2 = (bb & 1) ? up2(acc[2][bb >> 1]).y : up2(acc[2][bb >> 1]).x;
                        float v3 = (bb & 1) ? up2(acc[3][bb >> 1]).y : up2(acc[3][bb >> 1]).x;
                        *(float4*)&g_Gpart[ks][b0 + bb][obase] = make_float4(v0, v1, v2, v3);
                    }
                }
            }
            arrive_m(&g_sync[OFF_SUBGEMM + t * 25 * 64], bx % 25, 16,
                     &g_sync[OFF_GEMMROOT + t], 25, &g_sync[OFF_GEMMFLAG + t * 8 * 64]);
        }
    } else if (bx < GEMM_BLOCKS + GATE_BLOCKS) {
        // ============ dedicated gates role: one block per b ============
        int gb = bx - GEMM_BLOCKS;
        for (int t = 0; t < Lsz; t++) {
            wait_flag_m(&g_sync[OFF_GEMMFLAG + t * 8 * 64], lane8);
            if (tf) wait_flag_m(&g_sync[OFF_BATCHFLAG + t * 8 * 64], lane8);
            const float* hprev = g_hHist[t];
            float*       hout  = g_hHist[t + 1];
            for (int j = tid; j < Hsz; j += 128) {
                float ir = bih[j], iz = bih[400 + j], in_ = bih[800 + j];
                float hr = bhh[j], hz = bhh[400 + j], hn = bhh[800 + j];
                if (tf) {
                    ir += g_giB[t][gb][j];
                    iz += g_giB[t][gb][400 + j];
                    in_ += g_giB[t][gb][800 + j];
                    #pragma unroll
                    for (int p = 0; p < NPART; p++) {
                        const float* P = &g_Gpart[p][gb][0];
                        hr += P[1200 + j]; hz += P[1600 + j]; hn += P[2000 + j];
                    }
                } else {
                    #pragma unroll
                    for (int p = 0; p < NPART; p++) {
                        const float* P = &g_Gpart[p][gb][0];
                        ir += P[j];        iz += P[400 + j];  in_ += P[800 + j];
                        hr += P[1200 + j]; hz += P[1600 + j]; hn += P[2000 + j];
                    }
                }
                float r = 1.f / (1.f + expf(-(ir + hr)));
                float z = 1.f / (1.f + expf(-(iz + hz)));
                float n = tanhf(in_ + r * hn);
                hout[gb * Hsz + j] = (1.f - z) * n + z * hprev[gb * Hsz + j];
            }
            arrive_m(&g_sync[OFF_SUBH + (t + 1) * 8 * 64], gb >> 3, 8,
                     &g_sync[OFF_HROOT + t + 1], 8,
                     &g_sync[OFF_HFLAG + (t + 1) * 8 * 64]);
        }
    } else {
        // ============ score pipeline (consumes hFlag only) ============
        int fb = bx - GEMM_BLOCKS - GATE_BLOCKS;

        // ---- duty 1: batch gi unit fb (t-ordered; units 0..479) ----
        if (tf && fb < 480) {
            float (*As)[68] = (float(*)[68])pool;
            float (*Ws)[44] = (float(*)[44])(pool + 3400);
            int bt = fb / 30;
            int jbase = (fb % 30) * 40;
            const float* A = g_xB + (size_t)bt * BH;
            int tj = tid / 8, tb = tid % 8;
            int b0 = 8 * tb, j0 = 4 * tj;
            bool active = (tj < 10);

            unsigned long long acc[4][4];
            #pragma unroll
            for (int a = 0; a < 4; a++)
                #pragma unroll
                for (int p = 0; p < 4; p++) acc[a][p] = 0ULL;

            for (int kt = 0; kt < 8; kt++) {
                int kbase = kt * KC;
                __syncthreads();
                for (int i = tid; i < 1600; i += 128) {
                    int q = i >> 6, b = i & 63;
                    float2 v = *(const float2*)&A[b * Hsz + kbase + 2 * q];
                    As[2 * q + 0][b] = v.x;
                    As[2 * q + 1][b] = v.y;
                }
                for (int i = tid; i < 1000; i += 128) {
                    int q = i / 40, j = i % 40;
                    float2 v = *(const float2*)&Wih[(size_t)(jbase + j) * Hsz + kbase + 2 * q];
                    Ws[2 * q + 0][j] = v.x;
                    Ws[2 * q + 1][j] = v.y;
                }
                __syncthreads();
                if (active) {
                    #pragma unroll 5
                    for (int k = 0; k < KC; k++) {
                        float4 av0 = *(const float4*)&As[k][b0];
                        float4 av1 = *(const float4*)&As[k][b0 + 4];
                        float4 wv  = *(const float4*)&Ws[k][j0];
                        unsigned long long a01 = pk2(av0.x, av0.y);
                        unsigned long long a23 = pk2(av0.z, av0.w);
                        unsigned long long a45 = pk2(av1.x, av1.y);
                        unsigned long long a67 = pk2(av1.z, av1.w);
                        unsigned long long w0 = pk2(wv.x, wv.x);
                        unsigned long long w1 = pk2(wv.y, wv.y);
                        unsigned long long w2 = pk2(wv.z, wv.z);
                        unsigned long long w3 = pk2(wv.w, wv.w);
                        ffma2(acc[0][0], a01, w0); ffma2(acc[0][1], a23, w0);
                        ffma2(acc[0][2], a45, w0); ffma2(acc[0][3], a67, w0);
                        ffma2(acc[1][0], a01, w1); ffma2(acc[1][1], a23, w1);
                        ffma2(acc[1][2], a45, w1); ffma2(acc[1][3], a67, w1);
                        ffma2(acc[2][0], a01, w2); ffma2(acc[2][1], a23, w2);
                        ffma2(acc[2][2], a45, w2); ffma2(acc[2][3], a67, w2);
                        ffma2(acc[3][0], a01, w3); ffma2(acc[3][1], a23, w3);
                        ffma2(acc[3][2], a45, w3); ffma2(acc[3][3], a67, w3);
                    }
                }
            }
            if (active) {
                #pragma unroll
                for (int p = 0; p < 4; p++) {
                    float2 f0 = up2(acc[0][p]);
                    float2 f1 = up2(acc[1][p]);
                    float2 f2 = up2(acc[2][p]);
                    float2 f3 = up2(acc[3][p]);
                    *(float4*)&g_giB[bt][b0 + 2 * p][jbase + j0]     = make_float4(f0.x, f1.x, f2.x, f3.x);
                    *(float4*)&g_giB[bt][b0 + 2 * p + 1][jbase + j0] = make_float4(f0.y, f1.y, f2.y, f3.y);
                }
            }
            __threadfence();
            __syncthreads();
            if (tid == 0) {
                int old = atomicAdd(&g_sync[OFF_BATCHCNT + bt], 1);
                if (old == 29) set_flags(&g_sync[OFF_BATCHFLAG + bt * 8 * 64]);
            }
            __syncthreads();
        }

        // ---- duty 2: transpose stripe ----
        {
            float (*tile)[33] = (float(*)[33])pool;
            int tx = tid & 31, ty = tid >> 5;    // 32 x 4
            for (int tt = fb; tt < Bsz * 16 * 13; tt += SCORE_BLOCKS) {
                int b = tt / (16 * 13);
                int rem = tt % (16 * 13);
                int s0 = (rem / 13) * 32;
                int h0 = (rem % 13) * 32;
                __syncthreads();
                #pragma unroll
                for (int i = 0; i < 32; i += 4) {
                    int s = s0 + ty + i, h = h0 + tx;
                    if (h < Hsz) tile[ty + i][tx] = enc[((size_t)b * Ssz + s) * Hsz + h];
                }
                __syncthreads();
                #pragma unroll
                for (int i = 0; i < 32; i += 4) {
                    int h = h0 + ty + i, s = s0 + tx;
                    if (h < Hsz) g_encT[b][h][s] = tile[tx][ty + i];
                }
            }
        }
        arrive_m(&g_sync[OFF_TSUB], fb >> 4, 16, &g_sync[OFF_TROOT], 32,
                 &g_sync[OFF_TFLAG]);
        wait_flag_m(&g_sync[OFF_TFLAG], lane8);

        // ---- duty 3: score loop ----
        float* sh   = pool;
        float* redv = pool + 64;
        int*   redi = (int*)(pool + 192);
        float* flg  = pool + 320;

        int b  = fb >> 3;
        int hc = fb & 7;
        int len = lens[b];

        for (int t = 0; t < Lsz; t++) {
            int par = t & 1;
            wait_flag_m(&g_sync[OFF_HFLAG + (t + 1) * 8 * 64], lane8);
            if (t >= 2) wait_ge(&g_sync[OFF_TAILCNT + b * 64], t - 1);   // scpart reuse

            const float* hnew = g_hHist[t + 1];
            if (tid < HCW)
                sh[tid] = hnew[b * Hsz + hc * HCW + tid];
            __syncthreads();

            int s0 = 4 * tid;
            if (s0 < len) {
                const float4* ep = (const float4*)&g_encT[b][hc * HCW][0] + tid;
                float4 acc = make_float4(0.f, 0.f, 0.f, 0.f);
                #pragma unroll 10
                for (int h = 0; h < HCW; h++) {
                    float hv = sh[h];
                    float4 e = ep[(size_t)h * 128];
                    acc.x += e.x * hv; acc.y += e.y * hv;
                    acc.z += e.z * hv; acc.w += e.w * hv;
                }
                *(float4*)&g_scpart[par][hc][b][s0] = acc;
            }

            __threadfence();
            __syncthreads();
            if (tid == 0) {
                int old = atomicAdd(&g_sync[OFF_CNTBT + t * Bsz + b], 1);
                flg[0] = (old == HC - 1) ? 1.f : 0.f;
            }
            __syncthreads();
            bool last = (flg[0] != 0.f);

            if (last) {
                __threadfence();
                float v[4];
                #pragma unroll
                for (int q = 0; q < 4; q++) {
                    int s = tid + 128 * q;
                    if (s < len) {
                        float sum = 0.f;
                        #pragma unroll
                        for (int p = 0; p < HC; p++) sum += g_scpart[par][p][b][s];
                        v[q] = sum;
                    } else {
                        v[q] = -INFINITY;
                    }
                }
                float mv = v[0]; int mi = tid;
                #pragma unroll
                for (int q = 1; q < 4; q++)
                    if (v[q] > mv) { mv = v[q]; mi = tid + 128 * q; }
                redv[tid] = mv;
                redi[tid] = mi;
                __syncthreads();
                for (int st = 64; st > 0; st >>= 1) {
                    if (tid < st) {
                        float w2 = redv[tid + st];
                        int   i2 = redi[tid + st];
                        if (w2 > redv[tid] || (w2 == redv[tid] && i2 < redi[tid])) {
                            redv[tid] = w2;
                            redi[tid] = i2;
                        }
                    }
                    __syncthreads();
                }
                float m = redv[0];
                int amax = redi[0];
                __syncthreads();

                float e[4], lsum = 0.f;
                #pragma unroll
                for (int q = 0; q < 4; q++) {
                    e[q] = expf(v[q] - m);
                    lsum += e[q];
                }
                redv[tid] = lsum;
                __syncthreads();
                for (int st = 64; st > 0; st >>= 1) {
                    if (tid < st) redv[tid] += redv[tid + st];
                    __syncthreads();
                }
                float inv = 1.f / redv[0];

                float* orow = out + (size_t)b * Lsz * Vsz + (size_t)t * Vsz;
                #pragma unroll
                for (int q = 0; q < 4; q++) {
                    int s = tid + 128 * q;
                    if (s < len)
                        atomicAdd(&orow[uttrs[b * Ssz + s]], e[q] * inv);
                }

                if (tid == 0) {
                    int pred = uttrs[b * Ssz + amax];
                    if (write_preds)
                        out[(size_t)Bsz * Lsz * Vsz + (size_t)t * Bsz + b] = (float)pred;
                    ((int*)flg)[1] = tf ? targets[b * Lsz + t] : pred;
                }
                __syncthreads();
                if (!tf) {
                    int nxt = ((int*)flg)[1];
                    if (tid < 100)
                        ((float4*)(g_x + b * Hsz))[tid] =
                            ((const float4*)(emb + (size_t)nxt * Hsz))[tid];
                }
                // release scpart slot + (!tf) step-complete flag
                __threadfence();
                __syncthreads();
                if (tid == 0) {
                    atomicAdd(&g_sync[OFF_TAILCNT + b * 64], 1);
                    if (!tf) {
                        int old = atomicAdd(&g_sync[OFF_FUSEDCNT + t], 1);
                        if (old == Bsz - 1)
                            set_flags(&g_sync[OFF_FUSEDFLAG + t * 8 * 64]);
                    }
                }
            }
        }
    }
}

// ---------------- launch ----------------
extern "C" void kernel_launch(void* const* d_in, const int* in_sizes, int n_in,
                              void* d_out, int out_size) {
    const float* eh       = (const float*)d_in[0];
    const float* enc      = (const float*)d_in[1];
    const int*   lens     = (const int*)d_in[2];
    const int*   uttrs    = (const int*)d_in[3];
    const int*   targets  = (const int*)d_in[4];
    const int*   slot     = (const int*)d_in[5];
    const int*   use_tf   = (const int*)d_in[6];
    const float* emb      = (const float*)d_in[7];
    const float* slot_emb = (const float*)d_in[8];
    const float* Wih      = (const float*)d_in[9];
    const float* Whh      = (const float*)d_in[10];
    const float* bih      = (const float*)d_in[11];
    const float* bhh      = (const float*)d_in[12];
    float* out = (float*)d_out;

    int write_preds = out_size > Bsz * Lsz * Vsz;
    reset_kernel<<<1, 256>>>();
    persist_kernel<<<NBLK, 128>>>(eh, enc, lens, uttrs, targets, slot, use_tf,
                                  emb, slot_emb, Wih, Whh, bih, bhh,
                                  out, out_size, write_preds);
}